// round 7
// baseline (speedup 1.0000x reference)
#include <cuda_runtime.h>
#include <math_constants.h>

// SMPL nearest-neighbor skinning — exact-pruned spatial-grid argmin.
//
// Pipeline (all per launch, graph-capturable, zero allocations):
//   1. zero_counts      : clear cell histograms
//   2. vert_count       : cell id + rank per vertex (atomics)
//   3. point_count      : cell id + rank per point  (atomics)
//   4. scan_offsets     : exclusive prefix sums (1 CTA)
//   5. vert_scatter     : cell-ordered vertex table (x,y,z,|v|^2) + orig idx
//   6. point_scatter    : cell-ordered point visit order (warp coherence)
//   7. nn_kernel        : expanding-ring exact NN + skinning epilogue
//
// Exactness: every visited vertex's d2 uses the bit-identical reference
// rounding (dot = fma chain; d2 = add(fma(-2,dot,sx), sv); sv,sx mul/add).
// Winner = lexicographic min of (d2, original_index)  ==  jnp.argmin's
// first-min-index, independent of visit order. Pruning skips a cell only if
// lb*0.999-1e-4 > best, where lb is a geometric lower bound; the slack
// dominates the <=3e-5 abs rounding gap between computed d2 and true d2,
// so no skippable vertex can tie-or-beat the final winner.
//
// Output layout: [0,3n) x_bar | [3n,12n) rotation_bar | [12n,28n) T_fwd

static constexpr int   NC     = 24;
static constexpr int   NCELLS = NC * NC * NC;       // 13824
static constexpr float ORG    = -4.0f;
static constexpr float CS     = 8.0f / NC;          // 1/3
static constexpr float INV_CS = NC / 8.0f;          // 3.0
static constexpr int   MAXN   = 100000;
static constexpr int   MAXV   = 8192;

__device__ int    g_vcount[NCELLS];
__device__ int    g_vstart[NCELLS + 1];
__device__ int    g_vrank[MAXV];
__device__ int    g_vcell[MAXV];
__device__ float4 g_vs[MAXV];
__device__ int    g_vidx[MAXV];

__device__ int    g_pcount[NCELLS];
__device__ int    g_pstart[NCELLS + 1];
__device__ int    g_prank[MAXN];
__device__ int    g_pcell[MAXN];
__device__ int    g_order[MAXN];

__device__ __forceinline__ int cell_coord(float x) {
    int c = (int)floorf((x - ORG) * INV_CS);
    return min(NC - 1, max(0, c));
}

// ───────────── build kernels ─────────────
__global__ void zero_counts() {
    int i = blockIdx.x * blockDim.x + threadIdx.x;
    if (i < NCELLS) { g_vcount[i] = 0; g_pcount[i] = 0; }
}

__global__ void vert_count(const float* __restrict__ verts, int nv) {
    int j = blockIdx.x * blockDim.x + threadIdx.x;
    if (j >= nv) return;
    float x = verts[3 * j], y = verts[3 * j + 1], z = verts[3 * j + 2];
    int cid = (cell_coord(z) * NC + cell_coord(y)) * NC + cell_coord(x);
    g_vcell[j] = cid;
    g_vrank[j] = atomicAdd(&g_vcount[cid], 1);
}

__global__ void point_count(const float* __restrict__ xyz, int n) {
    int i = blockIdx.x * blockDim.x + threadIdx.x;
    if (i >= n) return;
    float x = xyz[3 * i], y = xyz[3 * i + 1], z = xyz[3 * i + 2];
    int cid = (cell_coord(z) * NC + cell_coord(y)) * NC + cell_coord(x);
    g_pcell[i] = cid;
    g_prank[i] = atomicAdd(&g_pcount[cid], 1);
}

__global__ void __launch_bounds__(1024) scan_offsets() {
    __shared__ int part[1024];
    const int t = threadIdx.x;
    const int CHUNK = (NCELLS + 1023) / 1024;   // 14
    // verts
    {
        int base = t * CHUNK, s = 0;
        for (int k = 0; k < CHUNK; ++k) { int i = base + k; if (i < NCELLS) s += g_vcount[i]; }
        part[t] = s;
        __syncthreads();
        for (int off = 1; off < 1024; off <<= 1) {
            int v = (t >= off) ? part[t - off] : 0;
            __syncthreads();
            part[t] += v;
            __syncthreads();
        }
        int excl = part[t] - s;
        for (int k = 0; k < CHUNK; ++k) {
            int i = base + k;
            if (i < NCELLS) { g_vstart[i] = excl; excl += g_vcount[i]; }
        }
        if (t == 1023) g_vstart[NCELLS] = part[1023];
        __syncthreads();
    }
    // points
    {
        int base = t * CHUNK, s = 0;
        for (int k = 0; k < CHUNK; ++k) { int i = base + k; if (i < NCELLS) s += g_pcount[i]; }
        part[t] = s;
        __syncthreads();
        for (int off = 1; off < 1024; off <<= 1) {
            int v = (t >= off) ? part[t - off] : 0;
            __syncthreads();
            part[t] += v;
            __syncthreads();
        }
        int excl = part[t] - s;
        for (int k = 0; k < CHUNK; ++k) {
            int i = base + k;
            if (i < NCELLS) { g_pstart[i] = excl; excl += g_pcount[i]; }
        }
        if (t == 1023) g_pstart[NCELLS] = part[1023];
    }
}

__global__ void vert_scatter(const float* __restrict__ verts, int nv) {
    int j = blockIdx.x * blockDim.x + threadIdx.x;
    if (j >= nv) return;
    float x = verts[3 * j], y = verts[3 * j + 1], z = verts[3 * j + 2];
    float sv = __fadd_rn(__fadd_rn(__fmul_rn(x, x), __fmul_rn(y, y)), __fmul_rn(z, z));
    int pos = g_vstart[g_vcell[j]] + g_vrank[j];
    g_vs[pos]   = make_float4(x, y, z, sv);
    g_vidx[pos] = j;
}

__global__ void point_scatter(int n) {
    int i = blockIdx.x * blockDim.x + threadIdx.x;
    if (i >= n) return;
    g_order[g_pstart[g_pcell[i]] + g_prank[i]] = i;
}

// ───────────── main kernel: exact pruned NN + epilogue ─────────────
__global__ void __launch_bounds__(256) nn_kernel(
    const float* __restrict__ xyz,
    const float* __restrict__ rot,
    const float* __restrict__ W,
    const float* __restrict__ bones,
    float* __restrict__ out,
    int n)
{
    __shared__ float sB[24 * 16];
    for (int j = threadIdx.x; j < 24 * 16; j += blockDim.x) sB[j] = bones[j];
    __syncthreads();

    int i = blockIdx.x * blockDim.x + threadIdx.x;
    if (i >= n) return;
    const int pid = g_order[i];

    const float px = xyz[3 * pid + 0];
    const float py = xyz[3 * pid + 1];
    const float pz = xyz[3 * pid + 2];
    const float sx = __fadd_rn(__fadd_rn(__fmul_rn(px, px), __fmul_rn(py, py)),
                               __fmul_rn(pz, pz));

    const int cx = cell_coord(px), cy = cell_coord(py), cz = cell_coord(pz);

    // distance from point to its (possibly clamped) own cell box
    float lox = ORG + cx * CS, loy = ORG + cy * CS, loz = ORG + cz * CS;
    float ddx = fmaxf(0.f, fmaxf(lox - px, px - (lox + CS)));
    float ddy = fmaxf(0.f, fmaxf(loy - py, py - (loy + CS)));
    float ddz = fmaxf(0.f, fmaxf(loz - pz, pz - (loz + CS)));
    const float delta = sqrtf(ddx * ddx + ddy * ddy + ddz * ddz);

    float best = CUDART_INF_F;
    int   bidx = 0x7FFFFFFF;

    for (int r = 0; r < NC; ++r) {
        // all cells at chebyshev radius r are >= (r-1)*CS - delta away
        float rl = fmaxf(0.f, (float)(r - 1) * CS - delta);
        if (rl * rl * 0.999f - 1e-4f > best) break;

        int z0 = max(cz - r, 0), z1 = min(cz + r, NC - 1);
        int y0 = max(cy - r, 0), y1 = min(cy + r, NC - 1);
        int x0 = max(cx - r, 0), x1 = min(cx + r, NC - 1);
        for (int z = z0; z <= z1; ++z) {
            int adz = abs(z - cz);
            for (int y = y0; y <= y1; ++y) {
                int ady = abs(y - cy);
                for (int x = x0; x <= x1; ++x) {
                    int adx = abs(x - cx);
                    if (max(adz, max(ady, adx)) != r) continue;   // shell only

                    // conservative box lower bound
                    float clx = ORG + x * CS, cly = ORG + y * CS, clz = ORG + z * CS;
                    float bx = fmaxf(0.f, fmaxf(clx - px, px - (clx + CS)));
                    float by = fmaxf(0.f, fmaxf(cly - py, py - (cly + CS)));
                    float bz = fmaxf(0.f, fmaxf(clz - pz, pz - (clz + CS)));
                    float lb = bx * bx + by * by + bz * bz;
                    if (lb * 0.999f - 1e-4f > best) continue;

                    int cid = (z * NC + y) * NC + x;
                    int s = g_vstart[cid], e = g_vstart[cid + 1];
                    for (int k = s; k < e; ++k) {
                        float4 v = g_vs[k];
                        float dot = __fmaf_rn(px, v.x, 0.0f);
                        dot = __fmaf_rn(py, v.y, dot);
                        dot = __fmaf_rn(pz, v.z, dot);
                        float d2 = __fadd_rn(__fmaf_rn(-2.0f, dot, sx), v.w);
                        int idx = g_vidx[k];
                        bool better = (d2 < best) || (d2 == best && idx < bidx);
                        best = better ? d2 : best;
                        bidx = better ? idx : bidx;
                    }
                }
            }
        }
    }

    // ── skinning epilogue ──
    float T[16];
    #pragma unroll
    for (int k = 0; k < 16; ++k) T[k] = 0.0f;

    const float* wrow = W + (size_t)bidx * 24;
    #pragma unroll
    for (int j = 0; j < 24; ++j) {
        float wj = __ldg(wrow + j);
        #pragma unroll
        for (int k = 0; k < 16; ++k) T[k] = fmaf(wj, sB[j * 16 + k], T[k]);
    }

    // x_bar = T[:3,:] @ [x,1]
    #pragma unroll
    for (int ii = 0; ii < 3; ++ii) {
        float v = T[4 * ii + 3];
        v = fmaf(T[4 * ii + 0], px, v);
        v = fmaf(T[4 * ii + 1], py, v);
        v = fmaf(T[4 * ii + 2], pz, v);
        out[3 * pid + ii] = v;
    }

    // quaternion -> rotation matrix
    const float4 q = *reinterpret_cast<const float4*>(rot + 4 * pid);
    float qn = rsqrtf(q.x * q.x + q.y * q.y + q.z * q.z + q.w * q.w);
    float qr = q.x * qn, qx = q.y * qn, qy = q.z * qn, qz = q.w * qn;

    float R[3][3];
    R[0][0] = 1.0f - 2.0f * (qy * qy + qz * qz);
    R[0][1] = 2.0f * (qx * qy - qr * qz);
    R[0][2] = 2.0f * (qx * qz + qr * qy);
    R[1][0] = 2.0f * (qx * qy + qr * qz);
    R[1][1] = 1.0f - 2.0f * (qx * qx + qz * qz);
    R[1][2] = 2.0f * (qy * qz - qr * qx);
    R[2][0] = 2.0f * (qx * qz - qr * qy);
    R[2][1] = 2.0f * (qy * qz + qr * qx);
    R[2][2] = 1.0f - 2.0f * (qx * qx + qy * qy);

    float* out_R = out + (size_t)3 * n;
    #pragma unroll
    for (int ii = 0; ii < 3; ++ii) {
        #pragma unroll
        for (int k = 0; k < 3; ++k) {
            float v = T[4 * ii + 0] * R[0][k];
            v = fmaf(T[4 * ii + 1], R[1][k], v);
            v = fmaf(T[4 * ii + 2], R[2][k], v);
            out_R[9 * pid + 3 * ii + k] = v;
        }
    }

    float4* out_T = reinterpret_cast<float4*>(out + (size_t)12 * n) + (size_t)4 * pid;
    #pragma unroll
    for (int k = 0; k < 4; ++k)
        out_T[k] = make_float4(T[4 * k + 0], T[4 * k + 1], T[4 * k + 2], T[4 * k + 3]);
}

extern "C" void kernel_launch(void* const* d_in, const int* in_sizes, int n_in,
                              void* d_out, int out_size)
{
    const float* xyz   = (const float*)d_in[0];
    const float* rot   = (const float*)d_in[1];
    const float* verts = (const float*)d_in[2];
    const float* W     = (const float*)d_in[3];
    const float* bones = (const float*)d_in[4];
    float* out = (float*)d_out;

    const int n  = in_sizes[0] / 3;   // 100000
    const int nv = in_sizes[2] / 3;   // 6890

    zero_counts<<<(NCELLS + 255) / 256, 256>>>();
    vert_count<<<(nv + 255) / 256, 256>>>(verts, nv);
    point_count<<<(n + 255) / 256, 256>>>(xyz, n);
    scan_offsets<<<1, 1024>>>();
    vert_scatter<<<(nv + 255) / 256, 256>>>(verts, nv);
    point_scatter<<<(n + 255) / 256, 256>>>(n);
    nn_kernel<<<(n + 255) / 256, 256>>>(xyz, rot, W, bones, out, n);
}

// round 8
// speedup vs baseline: 3.5475x; 3.5475x over previous
#include <cuda_runtime.h>
#include <math_constants.h>
#include <float.h>

// SMPL nearest-neighbor skinning — exact NN via Morton-sorted 2-level
// bounding-sphere pruning (108 supers x 8 groups x 8 verts), warp-convergent.
//
// Exactness: every VISITED vertex's d2 uses the bit-identical reference
// rounding (dot = fma chain; d2 = add(fma(-2,dot,sx), sv); sv,sx mul/add).
// Winner = lexicographic min (d2, original_index) == jnp.argmin first-index,
// independent of visit order. A sphere is skipped only if
//   dist(p,center) > s_best + rad,  s_best = sqrt(best+1e-4)*1.0001,
// which (with radius inflation) implies every contained vert's computed d2
// is STRICTLY greater than the final best — skipping cannot change the answer.
//
// Output layout: [0,3n) x_bar | [3n,12n) rotation_bar | [12n,28n) T_fwd

static constexpr int   NC     = 16;
static constexpr int   NCELLS = NC * NC * NC;   // 4096
static constexpr float ORG    = -4.0f;
static constexpr float INV_CS = 2.0f;           // cell size 0.5 over [-4,4]
static constexpr int   MAXN   = 100000;
static constexpr int   MAXVP  = 6896;           // padded vert count (mult of 8)
static constexpr int   NGRP   = MAXVP / 8;      // 862
static constexpr int   NSUP   = (NGRP + 7) / 8; // 108

__device__ int    g_vcount[NCELLS];
__device__ int    g_vstart[NCELLS + 1];
__device__ int    g_vrank[MAXVP];
__device__ int    g_vcellid[MAXVP];
__device__ float4 g_vs[MAXVP];      // sorted verts (x,y,z,|v|^2); pad w=+inf
__device__ int    g_vidx[MAXVP];    // original indices; pad INT_MAX

__device__ int    g_pcount[NCELLS];
__device__ int    g_pstart[NCELLS + 1];
__device__ int    g_prank[MAXN];
__device__ int    g_pcellid[MAXN];
__device__ int    g_order[MAXN];

__device__ float4 g_gb[NGRP];       // group bounds (cx,cy,cz,rad)
__device__ float4 g_sb[NSUP];       // super bounds

__device__ __forceinline__ int cell_coord(float x) {
    int c = (int)floorf((x - ORG) * INV_CS);
    return min(NC - 1, max(0, c));
}
__device__ __forceinline__ int spread4(int v) {
    return (v & 1) | ((v & 2) << 2) | ((v & 4) << 4) | ((v & 8) << 6);
}
__device__ __forceinline__ int morton_cell(float x, float y, float z) {
    return spread4(cell_coord(x)) | (spread4(cell_coord(y)) << 1)
         | (spread4(cell_coord(z)) << 2);
}

// ───────────── build kernels ─────────────
__global__ void zero_counts(int nv) {
    int i = blockIdx.x * blockDim.x + threadIdx.x;   // 4096 threads
    if (i < NCELLS) { g_vcount[i] = 0; g_pcount[i] = 0; }
    for (int k = i; k < MAXVP; k += NCELLS) {
        if (k >= nv) {
            g_vs[k]   = make_float4(0.f, 0.f, 0.f, CUDART_INF_F);
            g_vidx[k] = 0x7FFFFFFF;
        }
    }
}

__global__ void vert_count(const float* __restrict__ verts, int nv) {
    int j = blockIdx.x * blockDim.x + threadIdx.x;
    if (j >= nv) return;
    int cid = morton_cell(verts[3 * j], verts[3 * j + 1], verts[3 * j + 2]);
    g_vcellid[j] = cid;
    g_vrank[j] = atomicAdd(&g_vcount[cid], 1);
}

__global__ void point_count(const float* __restrict__ xyz, int n) {
    int i = blockIdx.x * blockDim.x + threadIdx.x;
    if (i >= n) return;
    int cid = morton_cell(xyz[3 * i], xyz[3 * i + 1], xyz[3 * i + 2]);
    g_pcellid[i] = cid;
    g_prank[i] = atomicAdd(&g_pcount[cid], 1);
}

__global__ void __launch_bounds__(1024) scan_offsets() {
    __shared__ int part[1024];
    const int t = threadIdx.x;
    const int CHUNK = NCELLS / 1024;   // 4
    {   // verts
        int base = t * CHUNK, s = 0;
        #pragma unroll
        for (int k = 0; k < CHUNK; ++k) s += g_vcount[base + k];
        part[t] = s;
        __syncthreads();
        for (int off = 1; off < 1024; off <<= 1) {
            int v = (t >= off) ? part[t - off] : 0;
            __syncthreads(); part[t] += v; __syncthreads();
        }
        int excl = part[t] - s;
        #pragma unroll
        for (int k = 0; k < CHUNK; ++k) { g_vstart[base + k] = excl; excl += g_vcount[base + k]; }
        if (t == 1023) g_vstart[NCELLS] = part[1023];
        __syncthreads();
    }
    {   // points
        int base = t * CHUNK, s = 0;
        #pragma unroll
        for (int k = 0; k < CHUNK; ++k) s += g_pcount[base + k];
        part[t] = s;
        __syncthreads();
        for (int off = 1; off < 1024; off <<= 1) {
            int v = (t >= off) ? part[t - off] : 0;
            __syncthreads(); part[t] += v; __syncthreads();
        }
        int excl = part[t] - s;
        #pragma unroll
        for (int k = 0; k < CHUNK; ++k) { g_pstart[base + k] = excl; excl += g_pcount[base + k]; }
        if (t == 1023) g_pstart[NCELLS] = part[1023];
    }
}

__global__ void vert_scatter(const float* __restrict__ verts, int nv) {
    int j = blockIdx.x * blockDim.x + threadIdx.x;
    if (j >= nv) return;
    float x = verts[3 * j], y = verts[3 * j + 1], z = verts[3 * j + 2];
    float sv = __fadd_rn(__fadd_rn(__fmul_rn(x, x), __fmul_rn(y, y)), __fmul_rn(z, z));
    int pos = g_vstart[g_vcellid[j]] + g_vrank[j];
    g_vs[pos]   = make_float4(x, y, z, sv);
    g_vidx[pos] = j;
}

__global__ void point_scatter(int n) {
    int i = blockIdx.x * blockDim.x + threadIdx.x;
    if (i >= n) return;
    g_order[g_pstart[g_pcellid[i]] + g_prank[i]] = i;
}

__global__ void group_bounds() {
    int g = blockIdx.x * blockDim.x + threadIdx.x;
    if (g >= NGRP) return;
    float mnx = FLT_MAX, mny = FLT_MAX, mnz = FLT_MAX;
    float mxx = -FLT_MAX, mxy = -FLT_MAX, mxz = -FLT_MAX;
    bool any = false;
    #pragma unroll
    for (int k = 0; k < 8; ++k) {
        float4 v = g_vs[g * 8 + k];
        if (isinf(v.w)) continue;
        any = true;
        mnx = fminf(mnx, v.x); mxx = fmaxf(mxx, v.x);
        mny = fminf(mny, v.y); mxy = fmaxf(mxy, v.y);
        mnz = fminf(mnz, v.z); mxz = fmaxf(mxz, v.z);
    }
    if (!any) { g_gb[g] = make_float4(1e15f, 1e15f, 1e15f, 0.f); return; }
    float cx = 0.5f * (mnx + mxx), cy = 0.5f * (mny + mxy), cz = 0.5f * (mnz + mxz);
    float m2 = 0.f;
    #pragma unroll
    for (int k = 0; k < 8; ++k) {
        float4 v = g_vs[g * 8 + k];
        if (isinf(v.w)) continue;
        float dx = v.x - cx, dy = v.y - cy, dz = v.z - cz;
        m2 = fmaxf(m2, dx * dx + dy * dy + dz * dz);
    }
    g_gb[g] = make_float4(cx, cy, cz, sqrtf(m2) * 1.0001f + 1e-5f);
}

__global__ void super_bounds() {
    int s = blockIdx.x * blockDim.x + threadIdx.x;
    if (s >= NSUP) return;
    float mnx = FLT_MAX, mny = FLT_MAX, mnz = FLT_MAX;
    float mxx = -FLT_MAX, mxy = -FLT_MAX, mxz = -FLT_MAX;
    bool any = false;
    for (int k = 0; k < 8; ++k) {
        int g = s * 8 + k;
        if (g >= NGRP) break;
        float4 b = g_gb[g];
        if (b.x > 1e14f) continue;
        any = true;
        mnx = fminf(mnx, b.x - b.w); mxx = fmaxf(mxx, b.x + b.w);
        mny = fminf(mny, b.y - b.w); mxy = fmaxf(mxy, b.y + b.w);
        mnz = fminf(mnz, b.z - b.w); mxz = fmaxf(mxz, b.z + b.w);
    }
    if (!any) { g_sb[s] = make_float4(1e15f, 1e15f, 1e15f, 0.f); return; }
    float cx = 0.5f * (mnx + mxx), cy = 0.5f * (mny + mxy), cz = 0.5f * (mnz + mxz);
    float mr = 0.f;
    for (int k = 0; k < 8; ++k) {
        int g = s * 8 + k;
        if (g >= NGRP) break;
        float4 b = g_gb[g];
        if (b.x > 1e14f) continue;
        float dx = b.x - cx, dy = b.y - cy, dz = b.z - cz;
        mr = fmaxf(mr, sqrtf(dx * dx + dy * dy + dz * dz) + b.w);
    }
    g_sb[s] = make_float4(cx, cy, cz, mr * 1.0001f + 1e-5f);
}

// ───────────── main kernel ─────────────
__global__ void __launch_bounds__(256) nn_kernel(
    const float* __restrict__ xyz,
    const float* __restrict__ rot,
    const float* __restrict__ W,
    const float* __restrict__ bones,
    float* __restrict__ out,
    int n)
{
    __shared__ float4 sGB[NGRP];
    __shared__ float4 sSB[NSUP];
    __shared__ float  sB[24 * 16];
    for (int j = threadIdx.x; j < NGRP; j += blockDim.x) sGB[j] = g_gb[j];
    for (int j = threadIdx.x; j < NSUP; j += blockDim.x) sSB[j] = g_sb[j];
    for (int j = threadIdx.x; j < 24 * 16; j += blockDim.x) sB[j] = bones[j];
    __syncthreads();

    const int i = blockIdx.x * blockDim.x + threadIdx.x;
    const bool valid = (i < n);
    const int pid = g_order[valid ? i : (n - 1)];

    const float px = xyz[3 * pid + 0];
    const float py = xyz[3 * pid + 1];
    const float pz = xyz[3 * pid + 2];
    const float sx = __fadd_rn(__fadd_rn(__fmul_rn(px, px), __fmul_rn(py, py)),
                               __fmul_rn(pz, pz));

    float best = CUDART_INF_F;
    int   bidx = 0x7FFFFFFF;

    // exact per-vertex update for one group of 8 (reference rounding)
    auto eval_group = [&](int g) {
        #pragma unroll
        for (int k = 0; k < 8; ++k) {
            float4 v = g_vs[g * 8 + k];
            float dot = __fmaf_rn(px, v.x, 0.0f);
            dot = __fmaf_rn(py, v.y, dot);
            dot = __fmaf_rn(pz, v.z, dot);
            float d2 = __fadd_rn(__fmaf_rn(-2.0f, dot, sx), v.w);
            int idx = g_vidx[g * 8 + k];
            bool better = (d2 < best) || (d2 == best && idx < bidx);
            best = better ? d2 : best;
            bidx = better ? idx : bidx;
        }
    };

    // ── seed: nearest super center -> nearest group center -> full eval ──
    {
        float md = CUDART_INF_F; int bs = 0;
        for (int s = 0; s < NSUP; ++s) {
            float4 b = sSB[s];
            float dx = px - b.x, dy = py - b.y, dz = pz - b.z;
            float d = dx * dx + dy * dy + dz * dz;
            bool c = d < md; md = c ? d : md; bs = c ? s : bs;
        }
        float mg = CUDART_INF_F; int bg = 0;
        #pragma unroll
        for (int k = 0; k < 8; ++k) {
            int g = bs * 8 + k;
            float4 b = (g < NGRP) ? sGB[g] : make_float4(1e15f, 1e15f, 1e15f, 0.f);
            float dx = px - b.x, dy = py - b.y, dz = pz - b.z;
            float d = dx * dx + dy * dy + dz * dz;
            bool c = d < mg; mg = c ? d : mg; bg = c ? g : bg;
        }
        eval_group(bg);
    }

    float s_best = __fsqrt_rn(best + 1e-4f) * 1.0001f;

    // ── pruned pass over all supers (warp-convergent) ──
    for (int s = 0; s < NSUP; ++s) {
        float4 b = sSB[s];
        float dx = px - b.x, dy = py - b.y, dz = pz - b.z;
        float d = dx * dx + dy * dy + dz * dz;
        float thr = s_best + b.w;
        bool pass = d <= thr * thr;
        if (__ballot_sync(0xFFFFFFFFu, pass)) {
            #pragma unroll
            for (int k = 0; k < 8; ++k) {
                int g = s * 8 + k;
                if (g >= NGRP) break;
                float4 gb = sGB[g];
                float gx = px - gb.x, gy = py - gb.y, gz = pz - gb.z;
                float gd = gx * gx + gy * gy + gz * gz;
                float gthr = s_best + gb.w;
                bool gpass = gd <= gthr * gthr;
                if (__ballot_sync(0xFFFFFFFFu, gpass)) {
                    float old = best;
                    eval_group(g);
                    if (best < old) s_best = __fsqrt_rn(best + 1e-4f) * 1.0001f;
                }
            }
        }
    }

    if (!valid) return;

    // ── skinning epilogue ──
    float T[16];
    #pragma unroll
    for (int k = 0; k < 16; ++k) T[k] = 0.0f;
    const float* wrow = W + (size_t)bidx * 24;
    #pragma unroll
    for (int j = 0; j < 24; ++j) {
        float wj = __ldg(wrow + j);
        #pragma unroll
        for (int k = 0; k < 16; ++k) T[k] = fmaf(wj, sB[j * 16 + k], T[k]);
    }

    #pragma unroll
    for (int ii = 0; ii < 3; ++ii) {
        float v = T[4 * ii + 3];
        v = fmaf(T[4 * ii + 0], px, v);
        v = fmaf(T[4 * ii + 1], py, v);
        v = fmaf(T[4 * ii + 2], pz, v);
        out[3 * pid + ii] = v;
    }

    const float4 q = *reinterpret_cast<const float4*>(rot + 4 * pid);
    float qn = rsqrtf(q.x * q.x + q.y * q.y + q.z * q.z + q.w * q.w);
    float qr = q.x * qn, qx = q.y * qn, qy = q.z * qn, qz = q.w * qn;

    float R[3][3];
    R[0][0] = 1.0f - 2.0f * (qy * qy + qz * qz);
    R[0][1] = 2.0f * (qx * qy - qr * qz);
    R[0][2] = 2.0f * (qx * qz + qr * qy);
    R[1][0] = 2.0f * (qx * qy + qr * qz);
    R[1][1] = 1.0f - 2.0f * (qx * qx + qz * qz);
    R[1][2] = 2.0f * (qy * qz - qr * qx);
    R[2][0] = 2.0f * (qx * qz - qr * qy);
    R[2][1] = 2.0f * (qy * qz + qr * qx);
    R[2][2] = 1.0f - 2.0f * (qx * qx + qy * qy);

    float* out_R = out + (size_t)3 * n;
    #pragma unroll
    for (int ii = 0; ii < 3; ++ii) {
        #pragma unroll
        for (int k = 0; k < 3; ++k) {
            float v = T[4 * ii + 0] * R[0][k];
            v = fmaf(T[4 * ii + 1], R[1][k], v);
            v = fmaf(T[4 * ii + 2], R[2][k], v);
            out_R[9 * pid + 3 * ii + k] = v;
        }
    }

    float4* out_T = reinterpret_cast<float4*>(out + (size_t)12 * n) + (size_t)4 * pid;
    #pragma unroll
    for (int k = 0; k < 4; ++k)
        out_T[k] = make_float4(T[4 * k + 0], T[4 * k + 1], T[4 * k + 2], T[4 * k + 3]);
}

extern "C" void kernel_launch(void* const* d_in, const int* in_sizes, int n_in,
                              void* d_out, int out_size)
{
    const float* xyz   = (const float*)d_in[0];
    const float* rot   = (const float*)d_in[1];
    const float* verts = (const float*)d_in[2];
    const float* W     = (const float*)d_in[3];
    const float* bones = (const float*)d_in[4];
    float* out = (float*)d_out;

    const int n  = in_sizes[0] / 3;   // 100000
    const int nv = in_sizes[2] / 3;   // 6890

    zero_counts<<<NCELLS / 256, 256>>>(nv);
    vert_count<<<(nv + 255) / 256, 256>>>(verts, nv);
    point_count<<<(n + 255) / 256, 256>>>(xyz, n);
    scan_offsets<<<1, 1024>>>();
    vert_scatter<<<(nv + 255) / 256, 256>>>(verts, nv);
    point_scatter<<<(n + 255) / 256, 256>>>(n);
    group_bounds<<<(NGRP + 255) / 256, 256>>>();
    super_bounds<<<1, 128>>>();
    nn_kernel<<<(n + 255) / 256, 256>>>(xyz, rot, W, bones, out, n);
}